// round 1
// baseline (speedup 1.0000x reference)
#include <cuda_runtime.h>

#define NN 50000
#define NE 800000
#define FD 64

// ---------------- scratch (static device globals; no runtime alloc) ----------------
__device__ float g_deg[NN];
__device__ float g_dinv[NN];
__device__ float g_w[NE];
__device__ __align__(16) float g_tx1[NN * FD];
__device__ __align__(16) float g_s2[NN * FD];
__device__ __align__(16) float g_wc[7 * FD * FD];   // combined weights, [mat][k][f]
__device__ float g_bias[3 * FD];                    // bz, bh, blin

// ---------------- small prep kernels ----------------
__global__ void k_zero() {
    int i = blockIdx.x * blockDim.x + threadIdx.x;
    if (i < NN * FD) { g_tx1[i] = 0.f; g_s2[i] = 0.f; }
    if (i < NN) g_deg[i] = 0.f;
}

__global__ void k_prep(const float* __restrict__ Wxz, const float* __restrict__ bxz,
                       const float* __restrict__ bhz,
                       const float* __restrict__ Wxh, const float* __restrict__ bxh,
                       const float* __restrict__ bhh,
                       const float* __restrict__ Wlin, const float* __restrict__ blin) {
    int i = blockIdx.x * blockDim.x + threadIdx.x;
    if (i < FD * FD) {
        // Tx2 = 2*S2 - Tx0  =>  fold into W0' = W0 - W2, W2' = 2*W2
        g_wc[0 * 4096 + i] = Wxz[i] - Wxz[2 * 4096 + i];
        g_wc[1 * 4096 + i] = Wxz[4096 + i];
        g_wc[2 * 4096 + i] = 2.f * Wxz[2 * 4096 + i];
        g_wc[3 * 4096 + i] = Wxh[i] - Wxh[2 * 4096 + i];
        g_wc[4 * 4096 + i] = Wxh[4096 + i];
        g_wc[5 * 4096 + i] = 2.f * Wxh[2 * 4096 + i];
        g_wc[6 * 4096 + i] = Wlin[i];
    }
    if (i < FD) {
        g_bias[i]          = bxz[i] + bhz[i];   // H0=0 => cheb(H0)=b_hz
        g_bias[FD + i]     = bxh[i] + bhh[i];
        g_bias[2 * FD + i] = blin[i];
    }
}

__global__ void k_deg(const int* __restrict__ src, const float* __restrict__ ew) {
    int e = blockIdx.x * blockDim.x + threadIdx.x;
    if (e < NE) atomicAdd(&g_deg[src[e]], ew[e]);
}

__global__ void k_dinv() {
    int i = blockIdx.x * blockDim.x + threadIdx.x;
    if (i < NN) { float d = g_deg[i]; g_dinv[i] = (d > 0.f) ? rsqrtf(d) : 0.f; }
}

// vector reduction: one 16B L2 atomic for 4 floats (sm_90+)
__device__ __forceinline__ void red_v4(float* addr, float a, float b, float c, float d) {
    unsigned long long p = __cvta_generic_to_global(addr);
    asm volatile("red.global.add.v4.f32 [%0], {%1,%2,%3,%4};"
                 :: "l"(p), "f"(a), "f"(b), "f"(c), "f"(d) : "memory");
}

// ---------------- scatter passes: half-warp (16 lanes) per edge ----------------
__global__ void k_scatter1(const int* __restrict__ src, const int* __restrict__ dst,
                           const float* __restrict__ ew, const float* __restrict__ x) {
    int t = blockIdx.x * blockDim.x + threadIdx.x;
    int e = t >> 4, lane = t & 15;
    if (e >= NE) return;
    int s = src[e], d = dst[e];
    float w = -ew[e] * g_dinv[s] * g_dinv[d];
    if (lane == 0) g_w[e] = w;
    float4 v = reinterpret_cast<const float4*>(x)[s * 16 + lane];
    red_v4(&g_tx1[d * FD + lane * 4], w * v.x, w * v.y, w * v.z, w * v.w);
}

__global__ void k_scatter2(const int* __restrict__ src, const int* __restrict__ dst) {
    int t = blockIdx.x * blockDim.x + threadIdx.x;
    int e = t >> 4, lane = t & 15;
    if (e >= NE) return;
    int s = src[e], d = dst[e];
    float w = g_w[e];
    float4 v = reinterpret_cast<const float4*>(g_tx1)[s * 16 + lane];
    red_v4(&g_s2[d * FD + lane * 4], w * v.x, w * v.y, w * v.z, w * v.w);
}

// ---------------- fused dense kernel ----------------
// 148 persistent blocks x 512 threads. Weights (7 x 64x64) staged in smem once per block.
// Each warp owns 4 nodes; each lane owns a 2-feature pair (f = 2*lane).
#define SMEM_FLOATS (7 * 4096 + 192 + 64 * 192 + 64 * 64)

__global__ void __launch_bounds__(512, 1)
k_final(const float* __restrict__ x, float* __restrict__ out) {
    extern __shared__ float sm[];
    float* sW  = sm;                 // 7*4096
    float* sB  = sW + 7 * 4096;     // 192
    float* sTx = sB + 192;          // 64 nodes * (Tx0|Tx1|S2) * 64
    float* sH  = sTx + 64 * 192;    // 64 nodes * 64

    const int tid = threadIdx.x;
    for (int i = tid; i < 7 * 4096; i += 512) sW[i] = g_wc[i];
    for (int i = tid; i < 192; i += 512) sB[i] = g_bias[i];

    const int warp = tid >> 5, lane = tid & 31;
    const int f = lane * 2;
    const int ngroups = (NN + 63) / 64;

    for (int g = blockIdx.x; g < ngroups; g += gridDim.x) {
        const int base = g * 64;
        // stage Tx rows for 64 nodes (float4 coalesced)
        for (int i = tid; i < 1024; i += 512) {
            int node = i >> 4, q = i & 15;
            int n = base + node;
            float4 a, b, c;
            if (n < NN) {
                a = reinterpret_cast<const float4*>(x)[n * 16 + q];
                b = reinterpret_cast<const float4*>(g_tx1)[n * 16 + q];
                c = reinterpret_cast<const float4*>(g_s2)[n * 16 + q];
            } else {
                a = make_float4(0.f, 0.f, 0.f, 0.f); b = a; c = a;
            }
            reinterpret_cast<float4*>(sTx)[node * 48 + q]      = a;
            reinterpret_cast<float4*>(sTx)[node * 48 + 16 + q] = b;
            reinterpret_cast<float4*>(sTx)[node * 48 + 32 + q] = c;
        }
        __syncthreads();

        float2 az[4], ah[4];
        #pragma unroll
        for (int j = 0; j < 4; j++) {
            az[j].x = sB[f];      az[j].y = sB[f + 1];
            ah[j].x = sB[64 + f]; ah[j].y = sB[64 + f + 1];
        }
        const float* t = sTx + (warp * 4) * 192;

        #pragma unroll 4
        for (int k = 0; k < 64; k++) {
            float2 w0 = *(const float2*)&sW[k * 64 + f];
            float2 w1 = *(const float2*)&sW[4096 + k * 64 + f];
            float2 w2 = *(const float2*)&sW[8192 + k * 64 + f];
            float2 u0 = *(const float2*)&sW[12288 + k * 64 + f];
            float2 u1 = *(const float2*)&sW[16384 + k * 64 + f];
            float2 u2 = *(const float2*)&sW[20480 + k * 64 + f];
            #pragma unroll
            for (int j = 0; j < 4; j++) {
                float a0 = t[j * 192 + k];
                float a1 = t[j * 192 + 64 + k];
                float a2 = t[j * 192 + 128 + k];
                az[j].x = fmaf(a0, w0.x, fmaf(a1, w1.x, fmaf(a2, w2.x, az[j].x)));
                az[j].y = fmaf(a0, w0.y, fmaf(a1, w1.y, fmaf(a2, w2.y, az[j].y)));
                ah[j].x = fmaf(a0, u0.x, fmaf(a1, u1.x, fmaf(a2, u2.x, ah[j].x)));
                ah[j].y = fmaf(a0, u0.y, fmaf(a1, u1.y, fmaf(a2, u2.y, ah[j].y)));
            }
        }

        // gates + relu(H) -> smem
        #pragma unroll
        for (int j = 0; j < 4; j++) {
            int node = warp * 4 + j;
            float zx = 1.f / (1.f + __expf(-az[j].x));
            float zy = 1.f / (1.f + __expf(-az[j].y));
            // tanh via exp: 1 - 2/(e^{2x}+1), saturates correctly at +-inf
            float hx = 1.f - 2.f / (__expf(2.f * ah[j].x) + 1.f);
            float hy = 1.f - 2.f / (__expf(2.f * ah[j].y) + 1.f);
            float Hx = (1.f - zx) * hx;
            float Hy = (1.f - zy) * hy;
            sH[node * 64 + f]     = fmaxf(Hx, 0.f);
            sH[node * 64 + f + 1] = fmaxf(Hy, 0.f);
        }
        __syncthreads();

        float2 o[4];
        #pragma unroll
        for (int j = 0; j < 4; j++) { o[j].x = sB[128 + f]; o[j].y = sB[128 + f + 1]; }
        #pragma unroll 4
        for (int k = 0; k < 64; k++) {
            float2 wl = *(const float2*)&sW[6 * 4096 + k * 64 + f];
            #pragma unroll
            for (int j = 0; j < 4; j++) {
                float hv = sH[(warp * 4 + j) * 64 + k];
                o[j].x = fmaf(hv, wl.x, o[j].x);
                o[j].y = fmaf(hv, wl.y, o[j].y);
            }
        }
        #pragma unroll
        for (int j = 0; j < 4; j++) {
            int n = base + warp * 4 + j;
            if (n < NN) *(float2*)&out[n * 64 + f] = o[j];
        }
        __syncthreads();
    }
}

// ---------------- launch ----------------
extern "C" void kernel_launch(void* const* d_in, const int* in_sizes, int n_in,
                              void* d_out, int out_size) {
    const float* x    = (const float*)d_in[0];
    const int*   ei   = (const int*)d_in[1];
    const float* ew   = (const float*)d_in[2];
    const float* Wxz  = (const float*)d_in[3];
    const float* bxz  = (const float*)d_in[4];
    const float* bhz  = (const float*)d_in[6];   // W_hz unused (H0 = 0)
    const float* Wxh  = (const float*)d_in[11];
    const float* bxh  = (const float*)d_in[12];
    const float* bhh  = (const float*)d_in[14];  // W_hh unused
    const float* Wlin = (const float*)d_in[15];
    const float* blin = (const float*)d_in[16];
    float* out = (float*)d_out;

    const int* src = ei;
    const int* dst = ei + NE;

    cudaFuncSetAttribute(k_final, cudaFuncAttributeMaxDynamicSharedMemorySize,
                         SMEM_FLOATS * (int)sizeof(float));

    k_zero<<<(NN * FD + 255) / 256, 256>>>();
    k_prep<<<(FD * FD + 255) / 256, 256>>>(Wxz, bxz, bhz, Wxh, bxh, bhh, Wlin, blin);
    k_deg<<<(NE + 255) / 256, 256>>>(src, ew);
    k_dinv<<<(NN + 255) / 256, 256>>>();
    k_scatter1<<<(NE * 16 + 255) / 256, 256>>>(src, dst, ew, x);
    k_scatter2<<<(NE * 16 + 255) / 256, 256>>>(src, dst);
    k_final<<<148, 512, SMEM_FLOATS * (int)sizeof(float)>>>(x, out);
}

// round 2
// speedup vs baseline: 1.6357x; 1.6357x over previous
#include <cuda_runtime.h>

#define NN 50000
#define NE 800000
#define FD 64

// ---------------- scratch (static device globals; no runtime alloc) ----------------
__device__ float g_deg[NN];
__device__ float g_dinv[NN];
__device__ float g_w[NE];
__device__ __align__(16) float g_tx1[NN * FD];
__device__ __align__(16) float g_s2[NN * FD];
__device__ __align__(16) float g_wc[7 * FD * FD];   // combined weights, [mat][k][f]
__device__ float g_bias[3 * FD];                    // bz, bh, blin

// ---------------- f32x2 packed helpers (sm_103a dual-fp32 datapath) ----------------
__device__ __forceinline__ unsigned long long dup2(float a) {
    unsigned long long r;
    asm("mov.b64 %0, {%1, %1};" : "=l"(r) : "f"(a));
    return r;
}
__device__ __forceinline__ unsigned long long pk2(float a, float b) {
    unsigned long long r;
    asm("mov.b64 %0, {%1, %2};" : "=l"(r) : "f"(a), "f"(b));
    return r;
}
__device__ __forceinline__ void fma2(unsigned long long& d, unsigned long long a,
                                     unsigned long long b) {
    asm("fma.rn.f32x2 %0, %1, %2, %0;" : "+l"(d) : "l"(a), "l"(b));
}
__device__ __forceinline__ void unpk2(unsigned long long v, float& x, float& y) {
    asm("mov.b64 {%0, %1}, %2;" : "=f"(x), "=f"(y) : "l"(v));
}

// ---------------- prep kernels ----------------
__global__ void k_zero() {
    int i = blockIdx.x * blockDim.x + threadIdx.x;
    if (i < NN * FD) { g_tx1[i] = 0.f; g_s2[i] = 0.f; }
    if (i < NN) g_deg[i] = 0.f;
}

__global__ void k_deg(const int* __restrict__ src, const float* __restrict__ ew) {
    int e = blockIdx.x * blockDim.x + threadIdx.x;
    if (e < NE) atomicAdd(&g_deg[src[e]], ew[e]);
}

// dinv + weight combining + bias combining in one kernel
__global__ void k_prep(const float* __restrict__ Wxz, const float* __restrict__ bxz,
                       const float* __restrict__ bhz,
                       const float* __restrict__ Wxh, const float* __restrict__ bxh,
                       const float* __restrict__ bhh,
                       const float* __restrict__ Wlin, const float* __restrict__ blin) {
    int i = blockIdx.x * blockDim.x + threadIdx.x;
    if (i < NN) { float d = g_deg[i]; g_dinv[i] = (d > 0.f) ? rsqrtf(d) : 0.f; }
    if (i < FD * FD) {
        // Tx2 = 2*S2 - Tx0  =>  fold into W0' = W0 - W2, W2' = 2*W2
        g_wc[0 * 4096 + i] = Wxz[i] - Wxz[2 * 4096 + i];
        g_wc[1 * 4096 + i] = Wxz[4096 + i];
        g_wc[2 * 4096 + i] = 2.f * Wxz[2 * 4096 + i];
        g_wc[3 * 4096 + i] = Wxh[i] - Wxh[2 * 4096 + i];
        g_wc[4 * 4096 + i] = Wxh[4096 + i];
        g_wc[5 * 4096 + i] = 2.f * Wxh[2 * 4096 + i];
        g_wc[6 * 4096 + i] = Wlin[i];
    }
    if (i < FD) {
        g_bias[i]          = bxz[i] + bhz[i];   // H0=0 => cheb(H0)=b_hz
        g_bias[FD + i]     = bxh[i] + bhh[i];
        g_bias[2 * FD + i] = blin[i];
    }
}

// vector reduction: one 16B L2 atomic for 4 floats (sm_90+)
__device__ __forceinline__ void red_v4(float* addr, float a, float b, float c, float d) {
    unsigned long long p = __cvta_generic_to_global(addr);
    asm volatile("red.global.add.v4.f32 [%0], {%1,%2,%3,%4};"
                 :: "l"(p), "f"(a), "f"(b), "f"(c), "f"(d) : "memory");
}

// ---------------- scatter passes: half-warp (16 lanes) per edge ----------------
__global__ void k_scatter1(const int* __restrict__ src, const int* __restrict__ dst,
                           const float* __restrict__ ew, const float* __restrict__ x) {
    int t = blockIdx.x * blockDim.x + threadIdx.x;
    int e = t >> 4, lane = t & 15;
    if (e >= NE) return;
    int s = src[e], d = dst[e];
    float w = -ew[e] * g_dinv[s] * g_dinv[d];
    if (lane == 0) g_w[e] = w;
    float4 v = reinterpret_cast<const float4*>(x)[s * 16 + lane];
    red_v4(&g_tx1[d * FD + lane * 4], w * v.x, w * v.y, w * v.z, w * v.w);
}

__global__ void k_scatter2(const int* __restrict__ src, const int* __restrict__ dst) {
    int t = blockIdx.x * blockDim.x + threadIdx.x;
    int e = t >> 4, lane = t & 15;
    if (e >= NE) return;
    int s = src[e], d = dst[e];
    float w = g_w[e];
    float4 v = reinterpret_cast<const float4*>(g_tx1)[s * 16 + lane];
    red_v4(&g_s2[d * FD + lane * 4], w * v.x, w * v.y, w * v.z, w * v.w);
}

// ---------------- fused dense kernel ----------------
// 148 persistent blocks x 512 threads. Weights (7 x 64x64) staged in smem once.
// Each warp owns 4 nodes; each lane owns feature pair f = 2*lane, accumulated
// in packed f32x2 registers (weights in smem are already contiguous pairs).
#define SMEM_FLOATS (7 * 4096 + 192 + 64 * 192 + 64 * 64)

__global__ void __launch_bounds__(512, 1)
k_final(const float* __restrict__ x, float* __restrict__ out) {
    extern __shared__ float sm[];
    float* sW  = sm;                // 7*4096
    float* sB  = sW + 7 * 4096;    // 192
    float* sTx = sB + 192;         // 64 nodes * (Tx0|Tx1|S2) * 64
    float* sH  = sTx + 64 * 192;   // 64 nodes * 64

    const int tid = threadIdx.x;
    for (int i = tid; i < 7 * 4096; i += 512) sW[i] = g_wc[i];
    for (int i = tid; i < 192; i += 512) sB[i] = g_bias[i];

    const int warp = tid >> 5, lane = tid & 31;
    const int f = lane * 2;
    const int ngroups = (NN + 63) / 64;

    for (int g = blockIdx.x; g < ngroups; g += gridDim.x) {
        const int base = g * 64;
        // stage Tx rows for 64 nodes (float4 coalesced)
        for (int i = tid; i < 1024; i += 512) {
            int node = i >> 4, q = i & 15;
            int n = base + node;
            float4 a, b, c;
            if (n < NN) {
                a = reinterpret_cast<const float4*>(x)[n * 16 + q];
                b = reinterpret_cast<const float4*>(g_tx1)[n * 16 + q];
                c = reinterpret_cast<const float4*>(g_s2)[n * 16 + q];
            } else {
                a = make_float4(0.f, 0.f, 0.f, 0.f); b = a; c = a;
            }
            reinterpret_cast<float4*>(sTx)[node * 48 + q]      = a;
            reinterpret_cast<float4*>(sTx)[node * 48 + 16 + q] = b;
            reinterpret_cast<float4*>(sTx)[node * 48 + 32 + q] = c;
        }
        __syncthreads();

        unsigned long long az[4], ah[4];
        {
            unsigned long long bz = *(const unsigned long long*)&sB[f];
            unsigned long long bh = *(const unsigned long long*)&sB[64 + f];
            #pragma unroll
            for (int j = 0; j < 4; j++) { az[j] = bz; ah[j] = bh; }
        }
        const float* t = sTx + (warp * 4) * 192;

        #pragma unroll 4
        for (int k = 0; k < 64; k++) {
            // weights: contiguous float2 pairs in smem == packed b64 operands
            unsigned long long w0 = *(const unsigned long long*)&sW[k * 64 + f];
            unsigned long long w1 = *(const unsigned long long*)&sW[4096 + k * 64 + f];
            unsigned long long w2 = *(const unsigned long long*)&sW[8192 + k * 64 + f];
            unsigned long long u0 = *(const unsigned long long*)&sW[12288 + k * 64 + f];
            unsigned long long u1 = *(const unsigned long long*)&sW[16384 + k * 64 + f];
            unsigned long long u2 = *(const unsigned long long*)&sW[20480 + k * 64 + f];
            #pragma unroll
            for (int j = 0; j < 4; j++) {
                unsigned long long a0 = dup2(t[j * 192 + k]);
                unsigned long long a1 = dup2(t[j * 192 + 64 + k]);
                unsigned long long a2 = dup2(t[j * 192 + 128 + k]);
                fma2(az[j], a0, w0);
                fma2(az[j], a1, w1);
                fma2(az[j], a2, w2);
                fma2(ah[j], a0, u0);
                fma2(ah[j], a1, u1);
                fma2(ah[j], a2, u2);
            }
        }

        // gates + relu(H) -> smem
        #pragma unroll
        for (int j = 0; j < 4; j++) {
            int node = warp * 4 + j;
            float azx, azy, ahx, ahy;
            unpk2(az[j], azx, azy);
            unpk2(ah[j], ahx, ahy);
            float zx = 1.f / (1.f + __expf(-azx));
            float zy = 1.f / (1.f + __expf(-azy));
            float hx = 1.f - 2.f / (__expf(2.f * ahx) + 1.f);
            float hy = 1.f - 2.f / (__expf(2.f * ahy) + 1.f);
            sH[node * 64 + f]     = fmaxf((1.f - zx) * hx, 0.f);
            sH[node * 64 + f + 1] = fmaxf((1.f - zy) * hy, 0.f);
        }
        __syncthreads();

        unsigned long long o[4];
        {
            unsigned long long bl = *(const unsigned long long*)&sB[128 + f];
            #pragma unroll
            for (int j = 0; j < 4; j++) o[j] = bl;
        }
        #pragma unroll 4
        for (int k = 0; k < 64; k++) {
            unsigned long long wl = *(const unsigned long long*)&sW[6 * 4096 + k * 64 + f];
            #pragma unroll
            for (int j = 0; j < 4; j++) {
                unsigned long long hv = dup2(sH[(warp * 4 + j) * 64 + k]);
                fma2(o[j], hv, wl);
            }
        }
        #pragma unroll
        for (int j = 0; j < 4; j++) {
            int n = base + warp * 4 + j;
            if (n < NN) {
                float ox, oy;
                unpk2(o[j], ox, oy);
                out[n * 64 + f]     = ox;
                out[n * 64 + f + 1] = oy;
            }
        }
        __syncthreads();
    }
}

// ---------------- launch ----------------
extern "C" void kernel_launch(void* const* d_in, const int* in_sizes, int n_in,
                              void* d_out, int out_size) {
    const float* x    = (const float*)d_in[0];
    const int*   ei   = (const int*)d_in[1];
    const float* ew   = (const float*)d_in[2];
    const float* Wxz  = (const float*)d_in[3];
    const float* bxz  = (const float*)d_in[4];
    const float* bhz  = (const float*)d_in[6];   // W_hz unused (H0 = 0)
    const float* Wxh  = (const float*)d_in[11];
    const float* bxh  = (const float*)d_in[12];
    const float* bhh  = (const float*)d_in[14];  // W_hh unused
    const float* Wlin = (const float*)d_in[15];
    const float* blin = (const float*)d_in[16];
    float* out = (float*)d_out;

    const int* src = ei;
    const int* dst = ei + NE;

    cudaFuncSetAttribute(k_final, cudaFuncAttributeMaxDynamicSharedMemorySize,
                         SMEM_FLOATS * (int)sizeof(float));

    k_zero<<<(NN * FD + 255) / 256, 256>>>();
    k_deg<<<(NE + 255) / 256, 256>>>(src, ew);
    k_prep<<<(NN + 255) / 256, 256>>>(Wxz, bxz, bhz, Wxh, bxh, bhh, Wlin, blin);
    k_scatter1<<<(NE * 16 + 255) / 256, 256>>>(src, dst, ew, x);
    k_scatter2<<<(NE * 16 + 255) / 256, 256>>>(src, dst);
    k_final<<<148, 512, SMEM_FLOATS * (int)sizeof(float)>>>(x, out);
}